// round 3
// baseline (speedup 1.0000x reference)
#include <cuda_runtime.h>
#include <cstdint>

#define N_NODES 50000
#define N_EDGES 1600000
#define F_DIM 32
#define H_DIM 128
#define HID 512
#define OUTD 256

// Per-node precomputed layer-1 partials (scratch; __device__ globals are the
// allocation-guard-legal scratch mechanism).
__device__ float g_Pdst[(size_t)N_NODES * HID];
__device__ float g_Psrc[(size_t)N_NODES * HID];

// ---------------------------------------------------------------------------
// TF32 helpers
// ---------------------------------------------------------------------------
__device__ __forceinline__ float f2tf(float x) {
    uint32_t u;
    asm("cvt.rna.tf32.f32 %0, %1;" : "=r"(u) : "f"(x));
    return __uint_as_float(u);
}

__device__ __forceinline__ void mma8(float* d, const uint32_t* a,
                                     uint32_t b0, uint32_t b1) {
    asm volatile(
        "mma.sync.aligned.m16n8k8.row.col.f32.tf32.tf32.f32 "
        "{%0,%1,%2,%3},{%4,%5,%6,%7},{%8,%9},{%0,%1,%2,%3};"
        : "+f"(d[0]), "+f"(d[1]), "+f"(d[2]), "+f"(d[3])
        : "r"(a[0]), "r"(a[1]), "r"(a[2]), "r"(a[3]), "r"(b0), "r"(b1));
}

// ---------------------------------------------------------------------------
// Kernel 1: per-node layer-1 precompute.
// Pdst[n] = b1 + nf[n] @ W1[0:32] + nh[n] @ (W1[32:160] + W1[192:320])
// Psrc[n] = nf[n] @ W1[160:192]
// Block: 64 nodes x 512 output cols; 512 threads, each owns one column.
// ---------------------------------------------------------------------------
__global__ __launch_bounds__(512) void node_pre_kernel(
    const float* __restrict__ nf, const float* __restrict__ nh,
    const float* __restrict__ W1, const float* __restrict__ b1) {
    __shared__ float fs[64 * 161];  // [m][k], k in 0..159 (feat 0..31, hid 32..159)
    const int nb = blockIdx.x * 64;
    const int tid = threadIdx.x;

    for (int idx = tid; idx < 64 * 160; idx += 512) {
        int m = idx / 160, k = idx % 160;
        int n = nb + m;
        float v = 0.f;
        if (n < N_NODES)
            v = (k < F_DIM) ? nf[(size_t)n * F_DIM + k]
                            : nh[(size_t)n * H_DIM + (k - F_DIM)];
        fs[m * 161 + k] = v;
    }
    __syncthreads();

    const int j = tid;  // output column 0..511
    float acc[64];
    const float bj = b1[j];
#pragma unroll
    for (int m = 0; m < 64; m++) acc[m] = bj;

    // dst_feat contribution: rows 0..31
    for (int k = 0; k < F_DIM; k++) {
        float w = __ldg(W1 + (size_t)k * HID + j);
#pragma unroll
        for (int m = 0; m < 64; m++) acc[m] += fs[m * 161 + k] * w;
    }
    // dst_hid contribution (used twice): rows 32..159 + rows 192..319
    for (int h = 0; h < H_DIM; h++) {
        float w = __ldg(W1 + (size_t)(32 + h) * HID + j) +
                  __ldg(W1 + (size_t)(192 + h) * HID + j);
#pragma unroll
        for (int m = 0; m < 64; m++) acc[m] += fs[m * 161 + 32 + h] * w;
    }
    for (int m = 0; m < 64; m++) {
        int n = nb + m;
        if (n < N_NODES) g_Pdst[(size_t)n * HID + j] = acc[m];
    }

    // src_feat contribution: rows 160..191
#pragma unroll
    for (int m = 0; m < 64; m++) acc[m] = 0.f;
    for (int k = 0; k < F_DIM; k++) {
        float w = __ldg(W1 + (size_t)(160 + k) * HID + j);
#pragma unroll
        for (int m = 0; m < 64; m++) acc[m] += fs[m * 161 + k] * w;
    }
    for (int m = 0; m < 64; m++) {
        int n = nb + m;
        if (n < N_NODES) g_Psrc[(size_t)n * HID + j] = acc[m];
    }
}

// ---------------------------------------------------------------------------
// Kernel 2: fused per-edge layers 2+3 with TF32 mma.sync.
// Tile: 64 edges/block. 256 threads = 8 warps (2 m-warps x 4 n-warps).
// smem: hs = h1/h2 tile [64][516] fp32; wt = weight chunk [32][516] (or [32][260]).
// ---------------------------------------------------------------------------
#define HS_STRIDE 516
#define WT_STRIDE 516
#define WT3_STRIDE 260
#define SMEM_BYTES ((64 * HS_STRIDE + 32 * WT_STRIDE) * 4)

__global__ __launch_bounds__(256, 1) void edge_mlp_kernel(
    const int* __restrict__ src_idx, const int* __restrict__ dst_idx,
    const float* __restrict__ distance, const float* __restrict__ W1,
    const float* __restrict__ W2, const float* __restrict__ b2,
    const float* __restrict__ W3, const float* __restrict__ b3,
    float* __restrict__ out) {
    extern __shared__ float smem[];
    float* hs = smem;                       // 64 x 516
    float* wt = smem + 64 * HS_STRIDE;      // 32 x 516 (reused as 32 x 260)

    const int tid = threadIdx.x;
    const int lane = tid & 31;
    const int warp = tid >> 5;
    const int wm = warp >> 2;  // 0..1 -> rows wm*32..wm*32+31
    const int wn = warp & 3;   // 0..3 -> layer2 cols wn*128.., layer3 cols wn*64..
    const int ebase = blockIdx.x * 64;
    const int g = lane >> 2;   // groupID (row within 8)
    const int tg = lane & 3;   // threadID in group

    // ---- Stage h1 = relu(Pdst[dst] + Psrc[src] + dist * W1[320]) (tf32) ----
    {
        int m = tid >> 2;  // 0..63
        int q = tid & 3;   // column quarter
        int e = ebase + m;
        int d = dst_idx[e];
        int s = src_idx[e];
        float dist = distance[e];
        const float4* pd = (const float4*)(g_Pdst + (size_t)d * HID);
        const float4* ps = (const float4*)(g_Psrc + (size_t)s * HID);
        const float4* pw = (const float4*)(W1 + (size_t)320 * HID);
        float* hrow = hs + m * HS_STRIDE;
#pragma unroll 4
        for (int i = 0; i < 32; i++) {
            int jj = q * 32 + i;  // float4 index, col = jj*4
            float4 a = __ldg(pd + jj);
            float4 b = __ldg(ps + jj);
            float4 w = __ldg(pw + jj);
            float4 o;
            o.x = f2tf(fmaxf(fmaf(dist, w.x, a.x + b.x), 0.f));
            o.y = f2tf(fmaxf(fmaf(dist, w.y, a.y + b.y), 0.f));
            o.z = f2tf(fmaxf(fmaf(dist, w.z, a.z + b.z), 0.f));
            o.w = f2tf(fmaxf(fmaf(dist, w.w, a.w + b.w), 0.f));
            *(float4*)(hrow + jj * 4) = o;
        }
    }

    // ---- Layer 2: h2 = relu(h1 @ W2 + b2), M=64 N=512 K=512 ----
    float acc[2][16][4];
#pragma unroll
    for (int mt = 0; mt < 2; mt++)
#pragma unroll
        for (int nt = 0; nt < 16; nt++)
#pragma unroll
            for (int i = 0; i < 4; i++) acc[mt][nt][i] = 0.f;

    for (int kc = 0; kc < 16; kc++) {
        __syncthreads();
        // stage W2 rows [kc*32, kc*32+32) x 512, tf32-rounded
        for (int idx = tid; idx < 32 * 128; idx += 256) {
            int r = idx >> 7;
            int c4 = (idx & 127) << 2;
            float4 w = __ldg((const float4*)(W2 + ((size_t)(kc * 32 + r) << 9) + c4));
            float4 o;
            o.x = f2tf(w.x); o.y = f2tf(w.y); o.z = f2tf(w.z); o.w = f2tf(w.w);
            *(float4*)(wt + r * WT_STRIDE + c4) = o;
        }
        __syncthreads();

        const int kg = kc * 32;
#pragma unroll
        for (int s = 0; s < 4; s++) {
            uint32_t a[2][4];
#pragma unroll
            for (int mt = 0; mt < 2; mt++) {
                int r = wm * 32 + mt * 16 + g;
                int k = kg + s * 8 + tg;
                a[mt][0] = __float_as_uint(hs[r * HS_STRIDE + k]);
                a[mt][1] = __float_as_uint(hs[(r + 8) * HS_STRIDE + k]);
                a[mt][2] = __float_as_uint(hs[r * HS_STRIDE + k + 4]);
                a[mt][3] = __float_as_uint(hs[(r + 8) * HS_STRIDE + k + 4]);
            }
            int kl = s * 8 + tg;
#pragma unroll
            for (int nt = 0; nt < 16; nt++) {
                int c = wn * 128 + nt * 8 + g;
                uint32_t b0 = __float_as_uint(wt[kl * WT_STRIDE + c]);
                uint32_t b1 = __float_as_uint(wt[(kl + 4) * WT_STRIDE + c]);
                mma8(acc[0][nt], a[0], b0, b1);
                mma8(acc[1][nt], a[1], b0, b1);
            }
        }
    }

    // ---- Epilogue 2: relu(+b2), tf32, back into hs as h2 ----
    __syncthreads();
#pragma unroll
    for (int mt = 0; mt < 2; mt++)
#pragma unroll
        for (int nt = 0; nt < 16; nt++) {
            int r = wm * 32 + mt * 16 + g;
            int c = wn * 128 + nt * 8 + tg * 2;
            float ba = __ldg(b2 + c), bb = __ldg(b2 + c + 1);
            hs[r * HS_STRIDE + c]           = f2tf(fmaxf(acc[mt][nt][0] + ba, 0.f));
            hs[r * HS_STRIDE + c + 1]       = f2tf(fmaxf(acc[mt][nt][1] + bb, 0.f));
            hs[(r + 8) * HS_STRIDE + c]     = f2tf(fmaxf(acc[mt][nt][2] + ba, 0.f));
            hs[(r + 8) * HS_STRIDE + c + 1] = f2tf(fmaxf(acc[mt][nt][3] + bb, 0.f));
        }

    // ---- Layer 3: out = h2 @ W3 + b3, M=64 N=256 K=512 ----
    float acc3[2][8][4];
#pragma unroll
    for (int mt = 0; mt < 2; mt++)
#pragma unroll
        for (int nt = 0; nt < 8; nt++)
#pragma unroll
            for (int i = 0; i < 4; i++) acc3[mt][nt][i] = 0.f;

    for (int kc = 0; kc < 16; kc++) {
        __syncthreads();
        for (int idx = tid; idx < 32 * 64; idx += 256) {
            int r = idx >> 6;
            int c4 = (idx & 63) << 2;
            float4 w = __ldg((const float4*)(W3 + ((size_t)(kc * 32 + r) << 8) + c4));
            float4 o;
            o.x = f2tf(w.x); o.y = f2tf(w.y); o.z = f2tf(w.z); o.w = f2tf(w.w);
            *(float4*)(wt + r * WT3_STRIDE + c4) = o;
        }
        __syncthreads();

        const int kg = kc * 32;
#pragma unroll
        for (int s = 0; s < 4; s++) {
            uint32_t a[2][4];
#pragma unroll
            for (int mt = 0; mt < 2; mt++) {
                int r = wm * 32 + mt * 16 + g;
                int k = kg + s * 8 + tg;
                a[mt][0] = __float_as_uint(hs[r * HS_STRIDE + k]);
                a[mt][1] = __float_as_uint(hs[(r + 8) * HS_STRIDE + k]);
                a[mt][2] = __float_as_uint(hs[r * HS_STRIDE + k + 4]);
                a[mt][3] = __float_as_uint(hs[(r + 8) * HS_STRIDE + k + 4]);
            }
            int kl = s * 8 + tg;
#pragma unroll
            for (int nt = 0; nt < 8; nt++) {
                int c = wn * 64 + nt * 8 + g;
                uint32_t b0 = __float_as_uint(wt[kl * WT3_STRIDE + c]);
                uint32_t b1 = __float_as_uint(wt[(kl + 4) * WT3_STRIDE + c]);
                mma8(acc3[0][nt], a[0], b0, b1);
                mma8(acc3[1][nt], a[1], b0, b1);
            }
        }
    }

    // ---- Epilogue 3: + b3, write out ----
#pragma unroll
    for (int mt = 0; mt < 2; mt++)
#pragma unroll
        for (int nt = 0; nt < 8; nt++) {
            int r = wm * 32 + mt * 16 + g;
            int c = wn * 64 + nt * 8 + tg * 2;
            size_t row0 = (size_t)(ebase + r) * OUTD;
            size_t row8 = (size_t)(ebase + r + 8) * OUTD;
            float ba = __ldg(b3 + c), bb = __ldg(b3 + c + 1);
            out[row0 + c]     = acc3[mt][nt][0] + ba;
            out[row0 + c + 1] = acc3[mt][nt][1] + bb;
            out[row8 + c]     = acc3[mt][nt][2] + ba;
            out[row8 + c + 1] = acc3[mt][nt][3] + bb;
        }
}

// ---------------------------------------------------------------------------
extern "C" void kernel_launch(void* const* d_in, const int* in_sizes, int n_in,
                              void* d_out, int out_size) {
    const float* nf   = (const float*)d_in[0];
    const float* nh   = (const float*)d_in[1];
    const int*   src  = (const int*)d_in[2];
    const int*   dst  = (const int*)d_in[3];
    const float* dist = (const float*)d_in[4];
    const float* W1   = (const float*)d_in[5];
    const float* b1   = (const float*)d_in[6];
    const float* W2   = (const float*)d_in[7];
    const float* b2   = (const float*)d_in[8];
    const float* W3   = (const float*)d_in[9];
    const float* b3   = (const float*)d_in[10];
    float* out = (float*)d_out;

    static bool attr_set = false;
    if (!attr_set) {
        cudaFuncSetAttribute(edge_mlp_kernel,
                             cudaFuncAttributeMaxDynamicSharedMemorySize,
                             SMEM_BYTES);
        attr_set = true;
    }

    node_pre_kernel<<<(N_NODES + 63) / 64, 512>>>(nf, nh, W1, b1);
    edge_mlp_kernel<<<N_EDGES / 64, 256, SMEM_BYTES>>>(src, dst, dist, W1, W2,
                                                       b2, W3, b3, out);
}

// round 5
// speedup vs baseline: 1.0127x; 1.0127x over previous
#include <cuda_runtime.h>
#include <cstdint>

#define N_NODES 50000
#define N_EDGES 1600000
#define F_DIM 32
#define H_DIM 128
#define HID 512
#define OUTD 256

// Scratch (__device__ globals = allocation-guard-legal scratch)
__device__ float g_Pdst[(size_t)N_NODES * HID];
__device__ float g_Psrc[(size_t)N_NODES * HID];
__device__ float g_W2p[(size_t)HID * HID];   // tf32-pre-rounded W2 (row-major)
__device__ float g_W3p[(size_t)HID * OUTD];  // tf32-pre-rounded W3 (row-major)

__device__ __forceinline__ float f2tf(float x) {
    uint32_t u; asm("cvt.rna.tf32.f32 %0, %1;" : "=r"(u) : "f"(x));
    return __uint_as_float(u);
}
__device__ __forceinline__ uint32_t smem_u32(const void* p) {
    uint32_t a;
    asm("{ .reg .u64 t; cvta.to.shared.u64 t, %1; cvt.u32.u64 %0, t; }" : "=r"(a) : "l"(p));
    return a;
}
__device__ __forceinline__ void mma8(float* d, const uint32_t* a,
                                     uint32_t b0, uint32_t b1) {
    asm volatile(
        "mma.sync.aligned.m16n8k8.row.col.f32.tf32.tf32.f32 "
        "{%0,%1,%2,%3},{%4,%5,%6,%7},{%8,%9},{%0,%1,%2,%3};"
        : "+f"(d[0]), "+f"(d[1]), "+f"(d[2]), "+f"(d[3])
        : "r"(a[0]), "r"(a[1]), "r"(a[2]), "r"(a[3]), "r"(b0), "r"(b1));
}
#define CP16(sa, gp) asm volatile("cp.async.cg.shared.global [%0], [%1], 16;" :: "r"(sa), "l"(gp) : "memory")
#define CP_COMMIT() asm volatile("cp.async.commit_group;" ::: "memory")
#define CP_WAIT1() asm volatile("cp.async.wait_group 1;" ::: "memory")
#define CP_WAIT0() asm volatile("cp.async.wait_group 0;" ::: "memory")

// ---------------------------------------------------------------------------
// Kernel 1: per-node layer-1 precompute (same as R1 — proven).
// ---------------------------------------------------------------------------
__global__ __launch_bounds__(512) void node_pre_kernel(
    const float* __restrict__ nf, const float* __restrict__ nh,
    const float* __restrict__ W1, const float* __restrict__ b1) {
    __shared__ float fs[64 * 161];
    const int nb = blockIdx.x * 64, tid = threadIdx.x;
    for (int idx = tid; idx < 64 * 160; idx += 512) {
        int m = idx / 160, k = idx % 160, n = nb + m;
        float v = 0.f;
        if (n < N_NODES)
            v = (k < F_DIM) ? nf[(size_t)n * F_DIM + k] : nh[(size_t)n * H_DIM + (k - F_DIM)];
        fs[m * 161 + k] = v;
    }
    __syncthreads();
    const int j = tid;
    float acc[64];
    const float bj = b1[j];
#pragma unroll
    for (int m = 0; m < 64; m++) acc[m] = bj;
    for (int k = 0; k < F_DIM; k++) {
        float w = __ldg(W1 + (size_t)k * HID + j);
#pragma unroll
        for (int m = 0; m < 64; m++) acc[m] += fs[m * 161 + k] * w;
    }
    for (int h = 0; h < H_DIM; h++) {
        float w = __ldg(W1 + (size_t)(32 + h) * HID + j) + __ldg(W1 + (size_t)(192 + h) * HID + j);
#pragma unroll
        for (int m = 0; m < 64; m++) acc[m] += fs[m * 161 + 32 + h] * w;
    }
    for (int m = 0; m < 64; m++) { int n = nb + m; if (n < N_NODES) g_Pdst[(size_t)n * HID + j] = acc[m]; }
#pragma unroll
    for (int m = 0; m < 64; m++) acc[m] = 0.f;
    for (int k = 0; k < F_DIM; k++) {
        float w = __ldg(W1 + (size_t)(160 + k) * HID + j);
#pragma unroll
        for (int m = 0; m < 64; m++) acc[m] += fs[m * 161 + k] * w;
    }
    for (int m = 0; m < 64; m++) { int n = nb + m; if (n < N_NODES) g_Psrc[(size_t)n * HID + j] = acc[m]; }
}

// ---------------------------------------------------------------------------
// Kernel 2: tf32-round W2/W3 once (row-major copy).
// ---------------------------------------------------------------------------
__global__ void weight_prep_kernel(const float* __restrict__ W2, const float* __restrict__ W3) {
    int i = blockIdx.x * blockDim.x + threadIdx.x;
    if (i < HID * HID) g_W2p[i] = f2tf(W2[i]);
    else if (i < HID * HID + HID * OUTD) {
        int j = i - HID * HID;
        g_W3p[j] = f2tf(W3[j]);
    }
}

// ---------------------------------------------------------------------------
// Kernel 3: fused layers 2+3. 64 edges/block, 512 threads = 16 warps (2m x 8n).
// Weights streamed in 16-row chunks via double-buffered cp.async.
// smem (floats): hs[64*516] | wt[2][16*512] | b2s[512] | b3s[256] | w1s[512]
// ---------------------------------------------------------------------------
#define HS_STR 516
#define HS_F   (64 * HS_STR)          // 33024
#define WT_F   (16 * 512)             // 8192 per buffer
#define B2S_F  (HS_F + 2 * WT_F)      // 49408
#define B3S_F  (B2S_F + 512)
#define W1S_F  (B3S_F + 256)
#define SMEM_BYTES ((W1S_F + 512) * 4)  // 202752

__global__ __launch_bounds__(512, 1) void edge_mlp_kernel(
    const int* __restrict__ src_idx, const int* __restrict__ dst_idx,
    const float* __restrict__ distance, const float* __restrict__ W1,
    const float* __restrict__ b2, const float* __restrict__ b3,
    float* __restrict__ out) {
    extern __shared__ float sm[];
    float* hs = sm;
    float* b2s = sm + B2S_F;
    float* b3s = sm + B3S_F;
    float* w1s = sm + W1S_F;
    const uint32_t wtu = smem_u32(sm + HS_F);  // base of weight buffers

    const int tid = threadIdx.x, lane = tid & 31, warp = tid >> 5;
    const int wm = warp >> 3;   // 0..1 : rows wm*32..+32
    const int wn = warp & 7;    // 0..7 : layer2 cols wn*64.., layer3 cols wn*32..
    const int g = lane >> 2, tg = lane & 3;
    const int ebase = blockIdx.x * 64;

    // biases + W1 distance row
    b2s[tid & 511] = b2[tid & 511];
    if (tid < 512) w1s[tid] = W1[(size_t)320 * HID + tid];
    if (tid < 256) b3s[tid] = b3[tid];

    // prefetch W2 chunk 0 (32KB: 4 x 16B per thread)
    {
        const float* src = g_W2p;
#pragma unroll
        for (int i = 0; i < 4; i++) { int idx = tid + i * 512; CP16(wtu + idx * 16, src + idx * 4); }
        CP_COMMIT();
    }

    // ---- stage h1 = f2tf(relu(Pdst[dst] + Psrc[src] + dist*W1[320])) ----
    {
        const int m = tid >> 3, q = tid & 7;
        const int e = ebase + m;
        const int d = dst_idx[e], s = src_idx[e];
        const float dist = distance[e];
        const float4* pd = (const float4*)(g_Pdst + (size_t)d * HID);
        const float4* ps = (const float4*)(g_Psrc + (size_t)s * HID);
        float* hrow = hs + m * HS_STR;
#pragma unroll 4
        for (int i = 0; i < 16; i++) {
            int jj = i * 8 + q;
            float4 a = __ldg(pd + jj);
            float4 b = __ldg(ps + jj);
            float4 w = *(const float4*)(w1s + jj * 4);
            float4 o;
            o.x = f2tf(fmaxf(fmaf(dist, w.x, a.x + b.x), 0.f));
            o.y = f2tf(fmaxf(fmaf(dist, w.y, a.y + b.y), 0.f));
            o.z = f2tf(fmaxf(fmaf(dist, w.z, a.z + b.z), 0.f));
            o.w = f2tf(fmaxf(fmaf(dist, w.w, a.w + b.w), 0.f));
            *(float4*)(hrow + jj * 4) = o;
        }
    }
    __syncthreads();

    // ======================= Layer 2: K=512 in 32 chunks ====================
    float acc[2][8][4];
#pragma unroll
    for (int mt = 0; mt < 2; mt++)
#pragma unroll
        for (int nt = 0; nt < 8; nt++)
#pragma unroll
            for (int i = 0; i < 4; i++) acc[mt][nt][i] = 0.f;

    for (int cc = 0; cc < 32; cc++) {
        const float* wb = sm + HS_F + (cc & 1) * WT_F;
        if (cc < 31) {  // prefetch next chunk into other buffer
            const float* src = g_W2p + (size_t)(cc + 1) * WT_F;
            const uint32_t dstu = wtu + ((cc + 1) & 1) * (WT_F * 4);
#pragma unroll
            for (int i = 0; i < 4; i++) { int idx = tid + i * 512; CP16(dstu + idx * 16, src + idx * 4); }
            CP_COMMIT();
            CP_WAIT1();
        } else {
            CP_WAIT0();
        }
        __syncthreads();

#pragma unroll
        for (int s = 0; s < 2; s++) {
            const int k = cc * 16 + s * 8;
            uint32_t a[2][4];
#pragma unroll
            for (int mt = 0; mt < 2; mt++) {
                int r = wm * 32 + mt * 16 + g;
                a[mt][0] = __float_as_uint(hs[r * HS_STR + k + tg]);
                a[mt][1] = __float_as_uint(hs[(r + 8) * HS_STR + k + tg]);
                a[mt][2] = __float_as_uint(hs[r * HS_STR + k + tg + 4]);
                a[mt][3] = __float_as_uint(hs[(r + 8) * HS_STR + k + tg + 4]);
            }
            const int kl = s * 8 + tg;
#pragma unroll
            for (int nt = 0; nt < 8; nt++) {
                int c = wn * 64 + nt * 8 + g;
                uint32_t b0 = __float_as_uint(wb[kl * 512 + c]);
                uint32_t b1 = __float_as_uint(wb[(kl + 4) * 512 + c]);
                mma8(acc[0][nt], a[0], b0, b1);
                mma8(acc[1][nt], a[1], b0, b1);
            }
        }
        __syncthreads();
    }

    // prefetch W3 chunk 0 into buffer 0 (last read at cc=30; safe)
    {
        const float* src = g_W3p;
#pragma unroll
        for (int i = 0; i < 2; i++) { int idx = tid + i * 512; CP16(wtu + idx * 16, src + idx * 4); }
        CP_COMMIT();
    }

    // ---- epilogue 2: h2 = f2tf(relu(acc + b2)) back into hs ----
#pragma unroll
    for (int mt = 0; mt < 2; mt++)
#pragma unroll
        for (int nt = 0; nt < 8; nt++) {
            int r = wm * 32 + mt * 16 + g;
            int c = wn * 64 + nt * 8 + tg * 2;
            float ba = b2s[c], bb = b2s[c + 1];
            hs[r * HS_STR + c]           = f2tf(fmaxf(acc[mt][nt][0] + ba, 0.f));
            hs[r * HS_STR + c + 1]       = f2tf(fmaxf(acc[mt][nt][1] + bb, 0.f));
            hs[(r + 8) * HS_STR + c]     = f2tf(fmaxf(acc[mt][nt][2] + ba, 0.f));
            hs[(r + 8) * HS_STR + c + 1] = f2tf(fmaxf(acc[mt][nt][3] + bb, 0.f));
        }
    CP_WAIT0();
    __syncthreads();

    // ======================= Layer 3: K=512 in 32 chunks ====================
    float acc3[2][4][4];
#pragma unroll
    for (int mt = 0; mt < 2; mt++)
#pragma unroll
        for (int nt = 0; nt < 4; nt++)
#pragma unroll
            for (int i = 0; i < 4; i++) acc3[mt][nt][i] = 0.f;

    for (int cc = 0; cc < 32; cc++) {
        const float* wb = sm + HS_F + (cc & 1) * WT_F;  // only first 4096 floats used
        if (cc < 31) {
            const float* src = g_W3p + (size_t)(cc + 1) * (16 * OUTD);
            const uint32_t dstu = wtu + ((cc + 1) & 1) * (WT_F * 4);
#pragma unroll
            for (int i = 0; i < 2; i++) { int idx = tid + i * 512; CP16(dstu + idx * 16, src + idx * 4); }
            CP_COMMIT();
            CP_WAIT1();
        } else {
            CP_WAIT0();
        }
        __syncthreads();

#pragma unroll
        for (int s = 0; s < 2; s++) {
            const int k = cc * 16 + s * 8;
            uint32_t a[2][4];
#pragma unroll
            for (int mt = 0; mt < 2; mt++) {
                int r = wm * 32 + mt * 16 + g;
                a[mt][0] = __float_as_uint(hs[r * HS_STR + k + tg]);
                a[mt][1] = __float_as_uint(hs[(r + 8) * HS_STR + k + tg]);
                a[mt][2] = __float_as_uint(hs[r * HS_STR + k + tg + 4]);
                a[mt][3] = __float_as_uint(hs[(r + 8) * HS_STR + k + tg + 4]);
            }
            const int kl = s * 8 + tg;
#pragma unroll
            for (int nt = 0; nt < 4; nt++) {
                int c = wn * 32 + nt * 8 + g;
                uint32_t b0 = __float_as_uint(wb[kl * OUTD + c]);
                uint32_t b1 = __float_as_uint(wb[(kl + 4) * OUTD + c]);
                mma8(acc3[0][nt], a[0], b0, b1);
                mma8(acc3[1][nt], a[1], b0, b1);
            }
        }
        __syncthreads();
    }

    // ---- epilogue 3: out = acc3 + b3 ----
#pragma unroll
    for (int mt = 0; mt < 2; mt++)
#pragma unroll
        for (int nt = 0; nt < 4; nt++) {
            int r = wm * 32 + mt * 16 + g;
            int c = wn * 32 + nt * 8 + tg * 2;
            size_t row0 = (size_t)(ebase + r) * OUTD;
            size_t row8 = (size_t)(ebase + r + 8) * OUTD;
            float ba = b3s[c], bb = b3s[c + 1];
            out[row0 + c]     = acc3[mt][nt][0] + ba;
            out[row0 + c + 1] = acc3[mt][nt][1] + bb;
            out[row8 + c]     = acc3[mt][nt][2] + ba;
            out[row8 + c + 1] = acc3[mt][nt][3] + bb;
        }
}

// -----------------------------------------------------------------------------
extern "C" void kernel_launch(void* const* d_in, const int* in_sizes, int n_in,
                              void* d_out, int out_size) {
    const float* nf   = (const float*)d_in[0];
    const float* nh   = (const float*)d_in[1];
    const int*   src  = (const int*)d_in[2];
    const int*   dst  = (const int*)d_in[3];
    const float* dist = (const float*)d_in[4];
    const float* W1   = (const float*)d_in[5];
    const float* b1   = (const float*)d_in[6];
    const float* W2   = (const float*)d_in[7];
    const float* b2   = (const float*)d_in[8];
    const float* W3   = (const float*)d_in[9];
    const float* b3   = (const float*)d_in[10];
    float* out = (float*)d_out;

    static bool attr_set = false;
    if (!attr_set) {
        cudaFuncSetAttribute(edge_mlp_kernel,
                             cudaFuncAttributeMaxDynamicSharedMemorySize, SMEM_BYTES);
        attr_set = true;
    }
    node_pre_kernel<<<(N_NODES + 63) / 64, 512>>>(nf, nh, W1, b1);
    weight_prep_kernel<<<(HID * HID + HID * OUTD + 255) / 256, 256>>>(W2, W3);
    edge_mlp_kernel<<<N_EDGES / 64, 512, SMEM_BYTES>>>(src, dst, dist, W1, b2, b3, out);
}

// round 6
// speedup vs baseline: 1.3118x; 1.2954x over previous
#include <cuda_runtime.h>
#include <cstdint>

#define N_NODES 50000
#define N_EDGES 1600000
#define F_DIM 32
#define H_DIM 128
#define HID 512
#define OUTD 256

// Scratch (__device__ globals = allocation-guard-legal scratch)
__device__ float g_Pdst[(size_t)N_NODES * HID];
__device__ float g_Psrc[(size_t)N_NODES * HID];
__device__ float g_W2p[(size_t)HID * HID];   // tf32-pre-rounded W2 (row-major)
__device__ float g_W3p[(size_t)HID * OUTD];  // tf32-pre-rounded W3 (row-major)

__device__ __forceinline__ float f2tf(float x) {
    uint32_t u; asm("cvt.rna.tf32.f32 %0, %1;" : "=r"(u) : "f"(x));
    return __uint_as_float(u);
}
__device__ __forceinline__ uint32_t smem_u32(const void* p) {
    uint32_t a;
    asm("{ .reg .u64 t; cvta.to.shared.u64 t, %1; cvt.u32.u64 %0, t; }" : "=r"(a) : "l"(p));
    return a;
}
__device__ __forceinline__ void mma8(float* d, const uint32_t* a,
                                     uint32_t b0, uint32_t b1) {
    asm volatile(
        "mma.sync.aligned.m16n8k8.row.col.f32.tf32.tf32.f32 "
        "{%0,%1,%2,%3},{%4,%5,%6,%7},{%8,%9},{%0,%1,%2,%3};"
        : "+f"(d[0]), "+f"(d[1]), "+f"(d[2]), "+f"(d[3])
        : "r"(a[0]), "r"(a[1]), "r"(a[2]), "r"(a[3]), "r"(b0), "r"(b1));
}
#define CP16(sa, gp) asm volatile("cp.async.cg.shared.global [%0], [%1], 16;" :: "r"(sa), "l"(gp) : "memory")
#define CP_COMMIT() asm volatile("cp.async.commit_group;" ::: "memory")
#define CP_WAIT1() asm volatile("cp.async.wait_group 1;" ::: "memory")
#define CP_WAIT0() asm volatile("cp.async.wait_group 0;" ::: "memory")

// ---------------------------------------------------------------------------
// Kernel 1: per-node layer-1 precompute.
// ---------------------------------------------------------------------------
__global__ __launch_bounds__(512) void node_pre_kernel(
    const float* __restrict__ nf, const float* __restrict__ nh,
    const float* __restrict__ W1, const float* __restrict__ b1) {
    __shared__ float fs[64 * 161];
    const int nb = blockIdx.x * 64, tid = threadIdx.x;
    for (int idx = tid; idx < 64 * 160; idx += 512) {
        int m = idx / 160, k = idx % 160, n = nb + m;
        float v = 0.f;
        if (n < N_NODES)
            v = (k < F_DIM) ? nf[(size_t)n * F_DIM + k] : nh[(size_t)n * H_DIM + (k - F_DIM)];
        fs[m * 161 + k] = v;
    }
    __syncthreads();
    const int j = tid;
    float acc[64];
    const float bj = b1[j];
#pragma unroll
    for (int m = 0; m < 64; m++) acc[m] = bj;
    for (int k = 0; k < F_DIM; k++) {
        float w = __ldg(W1 + (size_t)k * HID + j);
#pragma unroll
        for (int m = 0; m < 64; m++) acc[m] += fs[m * 161 + k] * w;
    }
    for (int h = 0; h < H_DIM; h++) {
        float w = __ldg(W1 + (size_t)(32 + h) * HID + j) + __ldg(W1 + (size_t)(192 + h) * HID + j);
#pragma unroll
        for (int m = 0; m < 64; m++) acc[m] += fs[m * 161 + 32 + h] * w;
    }
    for (int m = 0; m < 64; m++) { int n = nb + m; if (n < N_NODES) g_Pdst[(size_t)n * HID + j] = acc[m]; }
#pragma unroll
    for (int m = 0; m < 64; m++) acc[m] = 0.f;
    for (int k = 0; k < F_DIM; k++) {
        float w = __ldg(W1 + (size_t)(160 + k) * HID + j);
#pragma unroll
        for (int m = 0; m < 64; m++) acc[m] += fs[m * 161 + k] * w;
    }
    for (int m = 0; m < 64; m++) { int n = nb + m; if (n < N_NODES) g_Psrc[(size_t)n * HID + j] = acc[m]; }
}

// ---------------------------------------------------------------------------
// Kernel 2: tf32-round W2/W3 once (row-major).
// ---------------------------------------------------------------------------
__global__ void weight_prep_kernel(const float* __restrict__ W2, const float* __restrict__ W3) {
    int i = blockIdx.x * blockDim.x + threadIdx.x;
    if (i < HID * HID) g_W2p[i] = f2tf(W2[i]);
    else if (i < HID * HID + HID * OUTD) {
        int j = i - HID * HID;
        g_W3p[j] = f2tf(W3[j]);
    }
}

// ---------------------------------------------------------------------------
// Kernel 3: fused layers 2+3. 64 edges/block, 512 threads = 16 warps (2m x 8n).
// Weights double-buffered via cp.async into PADDED-stride smem tiles
// (520 / 264 floats per k-row -> stride % 32 == 8 -> conflict-free B loads).
// ---------------------------------------------------------------------------
#define HS_STR 516
#define W2_STR 520
#define W3_STR 264
#define HS_F   (64 * HS_STR)            // 33024
#define WT_F   (16 * W2_STR)            // 8320 per buffer (layer3 uses 16*264 within)
#define B2S_F  (HS_F + 2 * WT_F)        // 49664
#define B3S_F  (B2S_F + 512)
#define W1S_F  (B3S_F + 256)
#define SMEM_BYTES ((W1S_F + 512) * 4)  // 203776

__global__ __launch_bounds__(512, 1) void edge_mlp_kernel(
    const int* __restrict__ src_idx, const int* __restrict__ dst_idx,
    const float* __restrict__ distance, const float* __restrict__ W1,
    const float* __restrict__ b2, const float* __restrict__ b3,
    float* __restrict__ out) {
    extern __shared__ float sm[];
    float* hs = sm;
    float* b2s = sm + B2S_F;
    float* b3s = sm + B3S_F;
    float* w1s = sm + W1S_F;
    const uint32_t wtu = smem_u32(sm + HS_F);

    const int tid = threadIdx.x, lane = tid & 31, warp = tid >> 5;
    const int wm = warp >> 3;   // 0..1
    const int wn = warp & 7;    // 0..7
    const int g = lane >> 2, tg = lane & 3;
    const int ebase = blockIdx.x * 64;

    b2s[tid & 511] = b2[tid & 511];
    if (tid < 512) w1s[tid] = W1[(size_t)320 * HID + tid];
    if (tid < 256) b3s[tid] = b3[tid];

    // prefetch W2 chunk 0 (rows 0..15) into buffer 0, padded stride
    {
#pragma unroll
        for (int i = 0; i < 4; i++) {
            int idx = tid + i * 512;             // 2048 chunks of 16B
            int row = idx >> 7, c4 = (idx & 127) << 2;
            CP16(wtu + (row * W2_STR + c4) * 4, g_W2p + row * 512 + c4);
        }
        CP_COMMIT();
    }

    // ---- stage h1 = f2tf(relu(Pdst[dst] + Psrc[src] + dist*W1[320])) ----
    {
        const int m = tid >> 3, q = tid & 7;
        const int e = ebase + m;
        const int d = dst_idx[e], s = src_idx[e];
        const float dist = distance[e];
        const float4* pd = (const float4*)(g_Pdst + (size_t)d * HID);
        const float4* ps = (const float4*)(g_Psrc + (size_t)s * HID);
        float* hrow = hs + m * HS_STR;
#pragma unroll 4
        for (int i = 0; i < 16; i++) {
            int jj = i * 8 + q;
            float4 a = __ldg(pd + jj);
            float4 b = __ldg(ps + jj);
            float4 w = *(const float4*)(w1s + jj * 4);
            float4 o;
            o.x = f2tf(fmaxf(fmaf(dist, w.x, a.x + b.x), 0.f));
            o.y = f2tf(fmaxf(fmaf(dist, w.y, a.y + b.y), 0.f));
            o.z = f2tf(fmaxf(fmaf(dist, w.z, a.z + b.z), 0.f));
            o.w = f2tf(fmaxf(fmaf(dist, w.w, a.w + b.w), 0.f));
            *(float4*)(hrow + jj * 4) = o;
        }
    }
    __syncthreads();

    // ======================= Layer 2: K=512 in 32 chunks ====================
    float acc[2][8][4];
#pragma unroll
    for (int mt = 0; mt < 2; mt++)
#pragma unroll
        for (int nt = 0; nt < 8; nt++)
#pragma unroll
            for (int i = 0; i < 4; i++) acc[mt][nt][i] = 0.f;

    for (int cc = 0; cc < 32; cc++) {
        const float* wb = sm + HS_F + (cc & 1) * WT_F;
        if (cc < 31) {
            const float* src = g_W2p + (size_t)(cc + 1) * (16 * 512);
            const uint32_t dstu = wtu + ((cc + 1) & 1) * (WT_F * 4);
#pragma unroll
            for (int i = 0; i < 4; i++) {
                int idx = tid + i * 512;
                int row = idx >> 7, c4 = (idx & 127) << 2;
                CP16(dstu + (row * W2_STR + c4) * 4, src + row * 512 + c4);
            }
            CP_COMMIT();
            CP_WAIT1();
        } else {
            CP_WAIT0();
        }
        __syncthreads();

#pragma unroll
        for (int s = 0; s < 2; s++) {
            const int k = cc * 16 + s * 8;
            uint32_t a[2][4];
#pragma unroll
            for (int mt = 0; mt < 2; mt++) {
                int r = wm * 32 + mt * 16 + g;
                a[mt][0] = __float_as_uint(hs[r * HS_STR + k + tg]);
                a[mt][1] = __float_as_uint(hs[(r + 8) * HS_STR + k + tg]);
                a[mt][2] = __float_as_uint(hs[r * HS_STR + k + tg + 4]);
                a[mt][3] = __float_as_uint(hs[(r + 8) * HS_STR + k + tg + 4]);
            }
            const int kl = s * 8 + tg;
#pragma unroll
            for (int nt = 0; nt < 8; nt++) {
                int c = wn * 64 + nt * 8 + g;
                uint32_t b0 = __float_as_uint(wb[kl * W2_STR + c]);
                uint32_t b1 = __float_as_uint(wb[(kl + 4) * W2_STR + c]);
                mma8(acc[0][nt], a[0], b0, b1);
                mma8(acc[1][nt], a[1], b0, b1);
            }
        }
        __syncthreads();
    }

    // prefetch W3 chunk 0 into buffer 0
    {
#pragma unroll
        for (int i = 0; i < 2; i++) {
            int idx = tid + i * 512;             // 1024 chunks of 16B
            int row = idx >> 6, c4 = (idx & 63) << 2;
            CP16(wtu + (row * W3_STR + c4) * 4, g_W3p + row * 256 + c4);
        }
        CP_COMMIT();
    }

    // ---- epilogue 2: h2 = f2tf(relu(acc + b2)) back into hs ----
#pragma unroll
    for (int mt = 0; mt < 2; mt++)
#pragma unroll
        for (int nt = 0; nt < 8; nt++) {
            int r = wm * 32 + mt * 16 + g;
            int c = wn * 64 + nt * 8 + tg * 2;
            float ba = b2s[c], bb = b2s[c + 1];
            hs[r * HS_STR + c]           = f2tf(fmaxf(acc[mt][nt][0] + ba, 0.f));
            hs[r * HS_STR + c + 1]       = f2tf(fmaxf(acc[mt][nt][1] + bb, 0.f));
            hs[(r + 8) * HS_STR + c]     = f2tf(fmaxf(acc[mt][nt][2] + ba, 0.f));
            hs[(r + 8) * HS_STR + c + 1] = f2tf(fmaxf(acc[mt][nt][3] + bb, 0.f));
        }
    CP_WAIT0();
    __syncthreads();

    // ======================= Layer 3: K=512 in 32 chunks ====================
    float acc3[2][4][4];
#pragma unroll
    for (int mt = 0; mt < 2; mt++)
#pragma unroll
        for (int nt = 0; nt < 4; nt++)
#pragma unroll
            for (int i = 0; i < 4; i++) acc3[mt][nt][i] = 0.f;

    for (int cc = 0; cc < 32; cc++) {
        const float* wb = sm + HS_F + (cc & 1) * WT_F;
        if (cc < 31) {
            const float* src = g_W3p + (size_t)(cc + 1) * (16 * 256);
            const uint32_t dstu = wtu + ((cc + 1) & 1) * (WT_F * 4);
#pragma unroll
            for (int i = 0; i < 2; i++) {
                int idx = tid + i * 512;
                int row = idx >> 6, c4 = (idx & 63) << 2;
                CP16(dstu + (row * W3_STR + c4) * 4, src + row * 256 + c4);
            }
            CP_COMMIT();
            CP_WAIT1();
        } else {
            CP_WAIT0();
        }
        __syncthreads();

#pragma unroll
        for (int s = 0; s < 2; s++) {
            const int k = cc * 16 + s * 8;
            uint32_t a[2][4];
#pragma unroll
            for (int mt = 0; mt < 2; mt++) {
                int r = wm * 32 + mt * 16 + g;
                a[mt][0] = __float_as_uint(hs[r * HS_STR + k + tg]);
                a[mt][1] = __float_as_uint(hs[(r + 8) * HS_STR + k + tg]);
                a[mt][2] = __float_as_uint(hs[r * HS_STR + k + tg + 4]);
                a[mt][3] = __float_as_uint(hs[(r + 8) * HS_STR + k + tg + 4]);
            }
            const int kl = s * 8 + tg;
#pragma unroll
            for (int nt = 0; nt < 4; nt++) {
                int c = wn * 32 + nt * 8 + g;
                uint32_t b0 = __float_as_uint(wb[kl * W3_STR + c]);
                uint32_t b1 = __float_as_uint(wb[(kl + 4) * W3_STR + c]);
                mma8(acc3[0][nt], a[0], b0, b1);
                mma8(acc3[1][nt], a[1], b0, b1);
            }
        }
        __syncthreads();
    }

    // ---- epilogue 3: out = acc3 + b3 ----
#pragma unroll
    for (int mt = 0; mt < 2; mt++)
#pragma unroll
        for (int nt = 0; nt < 4; nt++) {
            int r = wm * 32 + mt * 16 + g;
            int c = wn * 32 + nt * 8 + tg * 2;
            size_t row0 = (size_t)(ebase + r) * OUTD;
            size_t row8 = (size_t)(ebase + r + 8) * OUTD;
            float ba = b3s[c], bb = b3s[c + 1];
            out[row0 + c]     = acc3[mt][nt][0] + ba;
            out[row0 + c + 1] = acc3[mt][nt][1] + bb;
            out[row8 + c]     = acc3[mt][nt][2] + ba;
            out[row8 + c + 1] = acc3[mt][nt][3] + bb;
        }
}

// -----------------------------------------------------------------------------
extern "C" void kernel_launch(void* const* d_in, const int* in_sizes, int n_in,
                              void* d_out, int out_size) {
    const float* nf   = (const float*)d_in[0];
    const float* nh   = (const float*)d_in[1];
    const int*   src  = (const int*)d_in[2];
    const int*   dst  = (const int*)d_in[3];
    const float* dist = (const float*)d_in[4];
    const float* W1   = (const float*)d_in[5];
    const float* b1   = (const float*)d_in[6];
    const float* W2   = (const float*)d_in[7];
    const float* b2   = (const float*)d_in[8];
    const float* W3   = (const float*)d_in[9];
    const float* b3   = (const float*)d_in[10];
    float* out = (float*)d_out;

    static bool attr_set = false;
    if (!attr_set) {
        cudaFuncSetAttribute(edge_mlp_kernel,
                             cudaFuncAttributeMaxDynamicSharedMemorySize, SMEM_BYTES);
        attr_set = true;
    }
    node_pre_kernel<<<(N_NODES + 63) / 64, 512>>>(nf, nh, W1, b1);
    weight_prep_kernel<<<(HID * HID + HID * OUTD + 255) / 256, 256>>>(W2, W3);
    edge_mlp_kernel<<<N_EDGES / 64, 512, SMEM_BYTES>>>(src, dst, dist, W1, b2, b3, out);
}